// round 7
// baseline (speedup 1.0000x reference)
#include <cuda_runtime.h>
#include <cuda_bf16.h>
#include <cstdint>

// Fixed shapes from reference setup_inputs
#define BB 8
#define CC 64
#define NN 100000
#define RR 32
#define R3 (RR * RR * RR)            // 32768
#define VOX_ELEMS (BB * CC * R3)     // 16,777,216
#define PTS (BB * NN)                // 800,000

// Scratch (no device allocation allowed -> __device__ globals).
// CUDA zero-initializes __device__ globals at module load; the pipeline is
// SELF-CLEANING (transpose re-zeroes occupied voxels + counts after reading),
// so "g_voxT/g_cnt are zero on entry" holds for every call incl. graph replays.
__device__ float g_voxT[(size_t)BB * R3 * CC];   // [B][R3][C] transposed accum, 67MB
__device__ float g_mean[BB * 3];
__device__ int   g_idx[PTS];
__device__ int   g_cnt[BB * R3];

// ---------------------------------------------------------------------------
// K1: deterministic per-(batch,dim) mean — BIT-EXACT Round-1 algorithm.
// Summation ORDER is load-bearing: it sets the mean's low bits, which decide
// rint() voxel assignment for boundary points. Do not change it.
// ---------------------------------------------------------------------------
__global__ void mean_kernel(const float* __restrict__ coords) {
    __shared__ float sm[1024];
    int bd = blockIdx.x;                 // 0..23
    const float* p = coords + (size_t)bd * NN;
    float s = 0.f;
    for (int i = threadIdx.x; i < NN; i += blockDim.x) s += p[i];
    sm[threadIdx.x] = s;
    __syncthreads();
    for (int off = 512; off > 0; off >>= 1) {
        if (threadIdx.x < off) sm[threadIdx.x] += sm[threadIdx.x + off];
        __syncthreads();
    }
    if (threadIdx.x == 0) g_mean[bd] = sm[0] * (1.0f / (float)NN);
}

// ---------------------------------------------------------------------------
// K2: per-point normalize, write norm_coords, compute flat voxel idx, count.
// ---------------------------------------------------------------------------
__global__ void point_kernel(const float* __restrict__ coords,
                             float* __restrict__ norm_out) {
    int t = blockIdx.x * blockDim.x + threadIdx.x;
    if (t >= PTS) return;
    int b = t / NN;
    int n = t - b * NN;

    int vc[3];
#pragma unroll
    for (int d = 0; d < 3; d++) {
        float c = coords[(size_t)(b * 3 + d) * NN + n];
        // ((c - mean) + 1) / 2 * r, clip [0, r-1]; *0.5 and *32 are exact
        float v = (c - g_mean[b * 3 + d] + 1.0f) * 0.5f;
        v = v * 32.0f;
        v = fminf(fmaxf(v, 0.0f), 31.0f);
        norm_out[(size_t)(b * 3 + d) * NN + n] = v;
        vc[d] = (int)rintf(v);       // round-half-to-even == jnp.round
    }
    int flat = vc[0] * (RR * RR) + vc[1] * RR + vc[2];
    g_idx[t] = flat;
    atomicAdd(&g_cnt[b * R3 + flat], 1);
}

// ---------------------------------------------------------------------------
// K3: scatter-add features into transposed accumulator with v4 reductions
// (Round-5 proven: 93.8us, L2-RMW paced in-kernel — no async drain bleeding
// into the next kernel, unlike cp.reduce.async.bulk). One thread per point;
// 16x red.global.add.v4.f32. Feature loads coalesced across the warp.
// ---------------------------------------------------------------------------
__global__ void scatter_kernel(const float* __restrict__ feat) {
    int t = blockIdx.x * blockDim.x + threadIdx.x;
    if (t >= PTS) return;
    int b = t / NN;
    int n = t - b * NN;
    int idx = g_idx[t];

    const float* f = feat + (size_t)b * CC * NN + n;
    float* dst = g_voxT + ((size_t)b * R3 + idx) * CC;   // 256B-aligned (C=64)

#pragma unroll
    for (int cq = 0; cq < CC / 4; cq++) {
        float v0 = f[(size_t)(4 * cq + 0) * NN];
        float v1 = f[(size_t)(4 * cq + 1) * NN];
        float v2 = f[(size_t)(4 * cq + 2) * NN];
        float v3 = f[(size_t)(4 * cq + 3) * NN];
        asm volatile(
            "red.global.add.v4.f32 [%0], {%1, %2, %3, %4};"
            :: "l"(dst + 4 * cq), "f"(v0), "f"(v1), "f"(v2), "f"(v3)
            : "memory");
    }
}

// ---------------------------------------------------------------------------
// K4: tiled transpose [B][R3][C] -> [B][C][R3] with divide-by-count, PLUS
// self-cleaning: skips src reads for empty voxels (87.5% of the grid — points
// map into [8,24]^3) and re-zeroes occupied voxel rows and counts so the next
// call starts from a zeroed accumulator. Output fully written (poison-safe).
// Tile = 32 voxels x 64 channels. Block: 256 threads = (64, 4).
// ---------------------------------------------------------------------------
__global__ void transpose_kernel(float* __restrict__ vox) {
    __shared__ float tile[32][65];   // [v][c], pad kills bank conflicts
    __shared__ float sinv[32];
    __shared__ int   socc[32];

    int blk = blockIdx.x;            // b * (R3/32) + vtile
    int b = blk / (R3 / 32);
    int v0 = (blk - b * (R3 / 32)) * 32;

    int tx = threadIdx.x;            // 0..63 = channel
    int ty = threadIdx.y;            // 0..3
    int lin = ty * 64 + tx;          // 0..255

    if (lin < 32) {
        int cnt = g_cnt[b * R3 + v0 + lin];
        socc[lin] = cnt;
        sinv[lin] = 1.0f / fmaxf((float)cnt, 1.0f);
        if (cnt != 0) g_cnt[b * R3 + v0 + lin] = 0;   // self-clean counts
    }
    __syncthreads();

    // load (coalesced 64-float rows); empty voxels -> 0 without touching mem;
    // occupied rows re-zeroed after reading (self-clean accumulator)
    float* src = g_voxT + ((size_t)b * R3 + v0) * CC;
#pragma unroll
    for (int vv = 0; vv < 32; vv += 4) {
        int v = vv + ty;
        if (socc[v] != 0) {                       // uniform per warp
            tile[v][tx] = src[(size_t)v * CC + tx];
            src[(size_t)v * CC + tx] = 0.0f;
        } else {
            tile[v][tx] = 0.0f;
        }
    }
    __syncthreads();

    // store: per channel row, 32 consecutive voxels -> coalesced 128B
    float* dstb = vox + (size_t)b * CC * R3 + v0;
#pragma unroll
    for (int j = 0; j < 8; j++) {
        int elem = j * 256 + lin;    // 0..2047
        int c = elem >> 5;           // 0..63
        int v = elem & 31;           // 0..31
        dstb[(size_t)c * R3 + v] = tile[v][c] * sinv[v];
    }
}

// ---------------------------------------------------------------------------
extern "C" void kernel_launch(void* const* d_in, const int* in_sizes, int n_in,
                              void* d_out, int out_size) {
    const float* features = (const float*)d_in[0];  // [B, C, N]
    const float* coords   = (const float*)d_in[1];  // [B, 3, N]
    float* out = (float*)d_out;
    float* vox  = out;                 // [B, C, R, R, R]
    float* norm = out + VOX_ELEMS;     // [B, 3, N]

    // K1: deterministic mean (Round-1 bit-exact ordering)
    mean_kernel<<<BB * 3, 1024>>>(coords);
    // K2: normalize + index + histogram
    point_kernel<<<(PTS + 255) / 256, 256>>>(coords, norm);
    // K3: v4-RED scatter into (zero-invariant) transposed scratch
    scatter_kernel<<<(PTS + 255) / 256, 256>>>(features);
    // K4: transpose + divide into d_out, self-clean scratch + counts
    transpose_kernel<<<BB * (R3 / 32), dim3(64, 4)>>>(vox);
}

// round 9
// speedup vs baseline: 1.6905x; 1.6905x over previous
#include <cuda_runtime.h>
#include <cuda_bf16.h>
#include <cstdint>

// Fixed shapes from reference setup_inputs
#define BB 8
#define CC 64
#define NN 100000
#define RR 32
#define R3 (RR * RR * RR)            // 32768
#define VOX_ELEMS (BB * CC * R3)     // 16,777,216
#define PTS (BB * NN)                // 800,000

#define SPTS 128                     // points staged per scatter block
#define SROW 68                      // padded floats per staged point (272B, 16B-aligned)
#define NBLK ((NN + SPTS - 1) / SPTS)  // 782

// Scratch (no device allocation allowed -> __device__ globals)
__device__ float g_voxT[(size_t)BB * R3 * CC];   // [B][R3][C] transposed accum, 67MB
__device__ float g_mean[BB * 3];
__device__ int   g_idx[PTS];
__device__ int   g_cnt[BB * R3];

// ---------------------------------------------------------------------------
// K0: zero transposed accumulator + count histogram (R5-measured ~11us)
// ---------------------------------------------------------------------------
__global__ void zero_kernel() {
    int i = blockIdx.x * blockDim.x + threadIdx.x;
    if (i < VOX_ELEMS / 4) {
        ((float4*)g_voxT)[i] = make_float4(0.f, 0.f, 0.f, 0.f);
    }
    if (i < BB * R3) {
        g_cnt[i] = 0;
    }
}

// ---------------------------------------------------------------------------
// K1: deterministic per-(batch,dim) mean — BIT-EXACT Round-1 algorithm.
// Summation ORDER is load-bearing: it sets the mean's low bits, which decide
// rint() voxel assignment for boundary points. Do not change it.
// ---------------------------------------------------------------------------
__global__ void mean_kernel(const float* __restrict__ coords) {
    __shared__ float sm[1024];
    int bd = blockIdx.x;                 // 0..23
    const float* p = coords + (size_t)bd * NN;
    float s = 0.f;
    for (int i = threadIdx.x; i < NN; i += blockDim.x) s += p[i];
    sm[threadIdx.x] = s;
    __syncthreads();
    for (int off = 512; off > 0; off >>= 1) {
        if (threadIdx.x < off) sm[threadIdx.x] += sm[threadIdx.x + off];
        __syncthreads();
    }
    if (threadIdx.x == 0) g_mean[bd] = sm[0] * (1.0f / (float)NN);
}

// ---------------------------------------------------------------------------
// K2: per-point normalize, write norm_coords, compute flat voxel idx, count.
// ---------------------------------------------------------------------------
__global__ void point_kernel(const float* __restrict__ coords,
                             float* __restrict__ norm_out) {
    int t = blockIdx.x * blockDim.x + threadIdx.x;
    if (t >= PTS) return;
    int b = t / NN;
    int n = t - b * NN;

    int vc[3];
#pragma unroll
    for (int d = 0; d < 3; d++) {
        float c = coords[(size_t)(b * 3 + d) * NN + n];
        // ((c - mean) + 1) / 2 * r, clip [0, r-1]; *0.5 and *32 are exact
        float v = (c - g_mean[b * 3 + d] + 1.0f) * 0.5f;
        v = v * 32.0f;
        v = fminf(fmaxf(v, 0.0f), 31.0f);
        norm_out[(size_t)(b * 3 + d) * NN + n] = v;
        vc[d] = (int)rintf(v);       // round-half-to-even == jnp.round
    }
    int flat = vc[0] * (RR * RR) + vc[1] * RR + vc[2];
    g_idx[t] = flat;
    atomicAdd(&g_cnt[b * R3 + flat], 1);
}

// ---------------------------------------------------------------------------
// K3: scatter via TMA bulk-reduce (R6-inferred ~68us, faster than v4-RED's
// measured 93.8us). Each thread stages its point's 64 channels into smem
// (coalesced channel-strided loads across the warp), then issues ONE
// cp.reduce.async.bulk (256B, element-atomic f32 add) into the transposed
// accumulator. wait_group 0 before exit -> all RMWs retired at kernel end.
// ---------------------------------------------------------------------------
__global__ void scatter_kernel(const float* __restrict__ feat) {
    __shared__ __align__(16) float st[SPTS * SROW];   // 34,816 B

    int b = blockIdx.y;
    int n = blockIdx.x * SPTS + threadIdx.x;
    bool valid = n < NN;

    if (valid) {
        const float* f = feat + (size_t)b * CC * NN + n;
        float* row = st + threadIdx.x * SROW;
#pragma unroll
        for (int c = 0; c < CC; c++) {
            row[c] = f[(size_t)c * NN];
        }
        // order generic-proxy smem writes before async-proxy (TMA) read
        asm volatile("fence.proxy.async.shared::cta;" ::: "memory");

        int idx = g_idx[b * NN + n];
        float* dst = g_voxT + ((size_t)b * R3 + idx) * CC;   // 256B-aligned
        uint32_t saddr;
        asm("{ .reg .u64 t; cvta.to.shared.u64 t, %1; cvt.u32.u64 %0, t; }"
            : "=r"(saddr) : "l"(row));
        asm volatile(
            "cp.reduce.async.bulk.global.shared::cta.bulk_group.add.f32 "
            "[%0], [%1], %2;"
            :: "l"(dst), "r"(saddr), "r"(CC * 4) : "memory");
        asm volatile("cp.async.bulk.commit_group;" ::: "memory");
    }
    // ensure all reductions are complete/visible before kernel end
    asm volatile("cp.async.bulk.wait_group 0;" ::: "memory");
}

// ---------------------------------------------------------------------------
// K4: tiled transpose [B][R3][C] -> [B][C][R3] with divide-by-count.
// VERBATIM Round-5 version (unconditional loads, no self-clean) — the only
// transpose variant with a fast in-container measurement (~45us inferred).
// Tile = 32 voxels x 64 channels. Block: 256 threads = (64, 4).
// ---------------------------------------------------------------------------
__global__ void transpose_kernel(float* __restrict__ vox) {
    __shared__ float tile[32][65];   // [v][c], pad to kill bank conflicts
    __shared__ float sinv[32];

    int blk = blockIdx.x;            // b * (R3/32) + vtile
    int b = blk / (R3 / 32);
    int v0 = (blk - b * (R3 / 32)) * 32;

    int tx = threadIdx.x;            // 0..63 = channel
    int ty = threadIdx.y;            // 0..3

    int lin = ty * 64 + tx;          // 0..255
    if (lin < 32) {
        float cnt = (float)g_cnt[b * R3 + v0 + lin];
        sinv[lin] = 1.0f / fmaxf(cnt, 1.0f);
    }

    // load: rows of 64 consecutive floats -> coalesced
    const float* src = g_voxT + ((size_t)b * R3 + v0) * CC;
#pragma unroll
    for (int vv = 0; vv < 32; vv += 4) {
        int v = vv + ty;
        tile[v][tx] = src[(size_t)v * CC + tx];
    }
    __syncthreads();

    // store: for each channel row, 32 consecutive voxels -> coalesced 128B
    float* dstb = vox + (size_t)b * CC * R3 + v0;
#pragma unroll
    for (int j = 0; j < 8; j++) {
        int elem = j * 256 + lin;    // 0..2047
        int c = elem >> 5;           // 0..63
        int v = elem & 31;           // 0..31
        dstb[(size_t)c * R3 + v] = tile[v][c] * sinv[v];
    }
}

// ---------------------------------------------------------------------------
extern "C" void kernel_launch(void* const* d_in, const int* in_sizes, int n_in,
                              void* d_out, int out_size) {
    const float* features = (const float*)d_in[0];  // [B, C, N]
    const float* coords   = (const float*)d_in[1];  // [B, 3, N]
    float* out = (float*)d_out;
    float* vox  = out;                 // [B, C, R, R, R]
    float* norm = out + VOX_ELEMS;     // [B, 3, N]

    // K0: zero scratch accumulator + counts
    {
        int tot = VOX_ELEMS / 4;
        zero_kernel<<<(tot + 255) / 256, 256>>>();
    }
    // K1: deterministic mean (Round-1 bit-exact ordering)
    mean_kernel<<<BB * 3, 1024>>>(coords);
    // K2: normalize + index + histogram
    point_kernel<<<(PTS + 255) / 256, 256>>>(coords, norm);
    // K3: TMA bulk-reduce scatter into transposed scratch
    scatter_kernel<<<dim3(NBLK, BB), SPTS>>>(features);
    // K4: transpose + divide into d_out
    transpose_kernel<<<BB * (R3 / 32), dim3(64, 4)>>>(vox);
}